// round 1
// baseline (speedup 1.0000x reference)
#include <cuda_runtime.h>
#include <math.h>

#define S_   64
#define I_   128
#define NO_  64
#define K_   64
#define D_   64
#define B_   64
#define TLEN_ 256
#define THR_ 0.01f
#define NTHREADS 512

// softmax over 64 values held as float4 by a 16-thread subgroup (width-16 shuffles)
__device__ __forceinline__ float4 softmax16(float4 a) {
    float m = fmaxf(fmaxf(a.x, a.y), fmaxf(a.z, a.w));
    #pragma unroll
    for (int o = 8; o > 0; o >>= 1)
        m = fmaxf(m, __shfl_xor_sync(0xffffffffu, m, o, 16));
    float4 e;
    e.x = expf(a.x - m); e.y = expf(a.y - m);
    e.z = expf(a.z - m); e.w = expf(a.w - m);
    float s = e.x + e.y + e.z + e.w;
    #pragma unroll
    for (int o = 8; o > 0; o >>= 1)
        s += __shfl_xor_sync(0xffffffffu, s, o, 16);
    float inv = 1.0f / s;
    e.x *= inv; e.y *= inv; e.z *= inv; e.w *= inv;
    return e;
}

__global__ __launch_bounds__(NTHREADS, 1)
void fpt_kernel(const int*   __restrict__ seq,
                const float* __restrict__ Tt,   // [S,I,D,S]
                const float* __restrict__ Ot,   // [S,I,D,NO]
                const float* __restrict__ pg,   // [S,I,1]
                const float* __restrict__ pp,   // [S,I,1]
                const float* __restrict__ pv,   // [S,I,D]
                const float* __restrict__ initl,// [S]
                float*       __restrict__ out)  // [B,TLEN,NO]
{
    __shared__ float  content[K_ * D_];
    __shared__ float4 partO4[32 * 16];
    __shared__ float4 partT4[32 * 16];
    __shared__ float  state[S_];
    __shared__ float  nstate[S_];
    __shared__ float  pointer[K_];
    __shared__ float  stTop[D_];
    __shared__ float  wbuf[K_];
    __shared__ float  pushv[D_];
    __shared__ float  scal[4];

    const int tid  = threadIdx.x;
    const int b    = blockIdx.x;
    const int og   = tid & 15;     // float4 group over o/n (16 x float4 = 64)
    const int srow = tid >> 4;     // 0..31
    const int s1   = srow;
    const int s2   = srow + 32;

    // ---- init carry: state = softmax(init_logits), content = 0, pointer = e0
    if (tid < S_) stTop[tid] = initl[tid];
    __syncthreads();
    if (tid == 0) {
        float m = -1e30f;
        for (int i = 0; i < S_; i++) m = fmaxf(m, stTop[i]);
        float s = 0.f;
        for (int i = 0; i < S_; i++) { float e = expf(stTop[i] - m); wbuf[i] = e; s += e; }
        scal[2] = s;
    }
    __syncthreads();
    if (tid < S_) state[tid] = wbuf[tid] / scal[2];
    for (int e = tid; e < K_ * D_; e += NTHREADS) content[e] = 0.f;
    if (tid < K_) pointer[tid] = (tid == 0) ? 1.f : 0.f;
    __syncthreads();

    for (int t = 0; t < TLEN_; t++) {
        const int sym = seq[b * TLEN_ + t];

        // ---- phase 1: stack_top, gate scalars, push_v (disjoint warps)
        if (tid < D_) {
            float acc = 0.f;
            #pragma unroll
            for (int k = 0; k < K_; k++) acc += pointer[k] * content[k * D_ + tid];
            stTop[tid] = acc;
        } else if (tid < 96) {               // warp 2: push_s
            int l = tid - 64;
            float a = pg[l * I_ + sym] * state[l] + pg[(l + 32) * I_ + sym] * state[l + 32];
            #pragma unroll
            for (int o = 16; o > 0; o >>= 1) a += __shfl_xor_sync(0xffffffffu, a, o);
            if (l == 0) scal[0] = 1.f / (1.f + expf(-a));
        } else if (tid < 128) {              // warp 3: pop_s
            int l = tid - 96;
            float a = pp[l * I_ + sym] * state[l] + pp[(l + 32) * I_ + sym] * state[l + 32];
            #pragma unroll
            for (int o = 16; o > 0; o >>= 1) a += __shfl_xor_sync(0xffffffffu, a, o);
            if (l == 0) scal[1] = 1.f / (1.f + expf(-a));
        } else if (tid < 192) {              // warps 4-5: push_v = tanh(state @ pv[:,sym,:])
            int d = tid - 128;
            float acc = 0.f;
            #pragma unroll 8
            for (int s = 0; s < S_; s++) acc += state[s] * pv[(s * I_ + sym) * D_ + d];
            pushv[d] = tanhf(acc);
        }
        __syncthreads();

        // ---- phase 2: stream T and O slices, contract with stack_top
        const float4* O4a = (const float4*)(Ot + (size_t)(s1 * I_ + sym) * 4096);
        const float4* O4b = (const float4*)(Ot + (size_t)(s2 * I_ + sym) * 4096);
        const float4* T4a = (const float4*)(Tt + (size_t)(s1 * I_ + sym) * 4096);
        const float4* T4b = (const float4*)(Tt + (size_t)(s2 * I_ + sym) * 4096);
        float4 aO1 = make_float4(0.f, 0.f, 0.f, 0.f);
        float4 aO2 = aO1, aT1 = aO1, aT2 = aO1;
        #pragma unroll 4
        for (int d = 0; d < D_; d++) {
            const float td = stTop[d];
            const int ix = d * 16 + og;
            float4 v;
            v = O4a[ix]; aO1.x += td * v.x; aO1.y += td * v.y; aO1.z += td * v.z; aO1.w += td * v.w;
            v = O4b[ix]; aO2.x += td * v.x; aO2.y += td * v.y; aO2.z += td * v.z; aO2.w += td * v.w;
            v = T4a[ix]; aT1.x += td * v.x; aT1.y += td * v.y; aT1.z += td * v.z; aT1.w += td * v.w;
            v = T4b[ix]; aT2.x += td * v.x; aT2.y += td * v.y; aT2.z += td * v.z; aT2.w += td * v.w;
        }

        // per-s softmax, then weight by old state and stage partials
        float4 pO1 = softmax16(aO1);
        float4 pO2 = softmax16(aO2);
        float4 pT1 = softmax16(aT1);
        float4 pT2 = softmax16(aT2);
        const float st1 = state[s1], st2 = state[s2];
        float4 w;
        w.x = st1 * pO1.x + st2 * pO2.x; w.y = st1 * pO1.y + st2 * pO2.y;
        w.z = st1 * pO1.z + st2 * pO2.z; w.w = st1 * pO1.w + st2 * pO2.w;
        partO4[srow * 16 + og] = w;
        w.x = st1 * pT1.x + st2 * pT2.x; w.y = st1 * pT1.y + st2 * pT2.y;
        w.z = st1 * pT1.z + st2 * pT2.z; w.w = st1 * pT1.w + st2 * pT2.w;
        partT4[srow * 16 + og] = w;
        __syncthreads();

        // ---- phase 3: reduce over s-rows -> out_prob, new_state
        if (tid < 64) {
            const float* pO = (const float*)partO4;
            const float* pT = (const float*)partT4;
            float so = 0.f, sn = 0.f;
            #pragma unroll
            for (int r = 0; r < 32; r++) {
                so += pO[r * 64 + tid];
                sn += pT[r * 64 + tid];
            }
            out[((size_t)b * TLEN_ + t) * NO_ + tid] = so;
            nstate[tid] = sn;
        }

        // ---- pointer update (pop then push), content update
        float p = 0.f, pd = 0.f;
        if (tid < K_) {
            p  = pointer[tid];
            pd = (tid < K_ - 1) ? pointer[tid + 1] : 0.f;
        }
        __syncthreads();
        const float pops  = scal[1];
        const float pushs = scal[0];
        if (tid < K_) {
            if (pops > THR_) p = pops * pd + (1.f - pops) * p;
            pointer[tid] = p;
        }
        __syncthreads();
        float pu = 0.f;
        if (tid < K_) pu = (tid > 0) ? pointer[tid - 1] : 0.f;
        __syncthreads();
        if (tid < K_) {
            float q = pushs * pu + (1.f - pushs) * p;
            wbuf[tid] = q;
            if (pushs > THR_) pointer[tid] = q;
        }
        __syncthreads();

        if (pushs > THR_) {
            for (int e = tid; e < K_ * D_; e += NTHREADS) {
                int k = e >> 6, d = e & 63;
                float wk = wbuf[k];
                content[e] = content[e] * (1.f - wk) + pushv[d] * wk;
            }
        }
        if (tid < S_) state[tid] = nstate[tid];
        __syncthreads();
    }
}

extern "C" void kernel_launch(void* const* d_in, const int* in_sizes, int n_in,
                              void* d_out, int out_size)
{
    const int*   seq   = (const int*)  d_in[0]; // input_seq [B,TLEN] int32
    const float* Tt    = (const float*)d_in[1]; // T  [S,I,D,S]
    const float* Ot    = (const float*)d_in[2]; // O  [S,I,D,NO]
    const float* pgate = (const float*)d_in[3]; // push_gate [S,I,1]
    const float* pop   = (const float*)d_in[4]; // pop_gate  [S,I,1]
    const float* pval  = (const float*)d_in[5]; // push_value [S,I,D]
    const float* initl = (const float*)d_in[6]; // init_logits [S]
    float* out = (float*)d_out;                 // [B,TLEN,NO]

    fpt_kernel<<<B_, NTHREADS>>>(seq, Tt, Ot, pgate, pop, pval, initl, out);
}

// round 2
// speedup vs baseline: 1.3599x; 1.3599x over previous
#include <cuda_runtime.h>
#include <cuda_fp16.h>
#include <math.h>

#define S_   64
#define I_   128
#define NO_  64
#define K_   64
#define D_   64
#define B_   64
#define TLEN_ 256
#define THR_ 0.01f
#define NTHREADS 512

#define WELEM  ((size_t)S_ * I_ * D_ * S_)   // 33,554,432 per weight tensor
#define TOTAL4 (WELEM / 4)                   // float4 count

// fp16 copies of T and O, built once per launch (device globals: no allocation)
__device__ __half g_Th[WELEM];
__device__ __half g_Oh[WELEM];

__global__ __launch_bounds__(256)
void cvt_kernel(const float* __restrict__ Ts, const float* __restrict__ Os) {
    size_t i = (size_t)blockIdx.x * blockDim.x + threadIdx.x;
    if (i >= TOTAL4) return;
    float4 a = ((const float4*)Ts)[i];
    float4 b = ((const float4*)Os)[i];
    __half2 a0 = __floats2half2_rn(a.x, a.y);
    __half2 a1 = __floats2half2_rn(a.z, a.w);
    __half2 b0 = __floats2half2_rn(b.x, b.y);
    __half2 b1 = __floats2half2_rn(b.z, b.w);
    uint2 ua, ub;
    ua.x = *(unsigned*)&a0; ua.y = *(unsigned*)&a1;
    ub.x = *(unsigned*)&b0; ub.y = *(unsigned*)&b1;
    ((uint2*)g_Th)[i] = ua;
    ((uint2*)g_Oh)[i] = ub;
}

// softmax over 64 values held as float4 by a 16-thread subgroup (width-16 shuffles)
__device__ __forceinline__ float4 softmax16(float4 a) {
    float m = fmaxf(fmaxf(a.x, a.y), fmaxf(a.z, a.w));
    #pragma unroll
    for (int o = 8; o > 0; o >>= 1)
        m = fmaxf(m, __shfl_xor_sync(0xffffffffu, m, o, 16));
    float4 e;
    e.x = expf(a.x - m); e.y = expf(a.y - m);
    e.z = expf(a.z - m); e.w = expf(a.w - m);
    float s = e.x + e.y + e.z + e.w;
    #pragma unroll
    for (int o = 8; o > 0; o >>= 1)
        s += __shfl_xor_sync(0xffffffffu, s, o, 16);
    float inv = 1.0f / s;
    e.x *= inv; e.y *= inv; e.z *= inv; e.w *= inv;
    return e;
}

__global__ __launch_bounds__(NTHREADS, 1)
void fpt_kernel(const int*   __restrict__ seq,
                const float* __restrict__ pg,   // [S,I,1]
                const float* __restrict__ pp,   // [S,I,1]
                const float* __restrict__ pv,   // [S,I,D]
                const float* __restrict__ initl,// [S]
                float*       __restrict__ out)  // [B,TLEN,NO]
{
    __shared__ float  content[K_ * D_];
    __shared__ float4 partO4[32 * 16];
    __shared__ float4 partT4[32 * 16];
    __shared__ float  state[S_];
    __shared__ float  nstate[S_];
    __shared__ float  pointer[K_];
    __shared__ float  stTop[D_];
    __shared__ float  wbuf[K_];
    __shared__ float  pushv[D_];
    __shared__ float  scal[4];

    const int tid  = threadIdx.x;
    const int b    = blockIdx.x;
    const int og   = tid & 15;     // 16 x (4 halves) = 64 outputs per row
    const int srow = tid >> 4;     // 0..31
    const int s1   = srow;
    const int s2   = srow + 32;

    // ---- init carry
    if (tid < S_) stTop[tid] = initl[tid];
    __syncthreads();
    if (tid == 0) {
        float m = -1e30f;
        for (int i = 0; i < S_; i++) m = fmaxf(m, stTop[i]);
        float s = 0.f;
        for (int i = 0; i < S_; i++) { float e = expf(stTop[i] - m); wbuf[i] = e; s += e; }
        scal[2] = s;
    }
    __syncthreads();
    if (tid < S_) state[tid] = wbuf[tid] / scal[2];
    for (int e = tid; e < K_ * D_; e += NTHREADS) content[e] = 0.f;
    if (tid < K_) pointer[tid] = (tid == 0) ? 1.f : 0.f;
    __syncthreads();

    for (int t = 0; t < TLEN_; t++) {
        const int sym = seq[b * TLEN_ + t];

        // ---- phase 1: stack_top, gate scalars, push_v (disjoint warps)
        if (tid < D_) {
            float acc = 0.f;
            #pragma unroll
            for (int k = 0; k < K_; k++) acc += pointer[k] * content[k * D_ + tid];
            stTop[tid] = acc;
        } else if (tid < 96) {               // warp 2: push_s
            int l = tid - 64;
            float a = pg[l * I_ + sym] * state[l] + pg[(l + 32) * I_ + sym] * state[l + 32];
            #pragma unroll
            for (int o = 16; o > 0; o >>= 1) a += __shfl_xor_sync(0xffffffffu, a, o);
            if (l == 0) scal[0] = 1.f / (1.f + expf(-a));
        } else if (tid < 128) {              // warp 3: pop_s
            int l = tid - 96;
            float a = pp[l * I_ + sym] * state[l] + pp[(l + 32) * I_ + sym] * state[l + 32];
            #pragma unroll
            for (int o = 16; o > 0; o >>= 1) a += __shfl_xor_sync(0xffffffffu, a, o);
            if (l == 0) scal[1] = 1.f / (1.f + expf(-a));
        } else if (tid < 192) {              // warps 4-5: push_v = tanh(state @ pv[:,sym,:])
            int d = tid - 128;
            float acc = 0.f;
            #pragma unroll 8
            for (int s = 0; s < S_; s++) acc += state[s] * pv[(s * I_ + sym) * D_ + d];
            pushv[d] = tanhf(acc);
        }
        __syncthreads();

        // ---- phase 2: stream fp16 T and O slices, contract with stack_top
        // slice row for (s,sym): 64 halves = 16 x uint2 (4 halves each)
        const uint2* O2a = (const uint2*)(g_Oh + (size_t)(s1 * I_ + sym) * 4096);
        const uint2* O2b = (const uint2*)(g_Oh + (size_t)(s2 * I_ + sym) * 4096);
        const uint2* T2a = (const uint2*)(g_Th + (size_t)(s1 * I_ + sym) * 4096);
        const uint2* T2b = (const uint2*)(g_Th + (size_t)(s2 * I_ + sym) * 4096);
        float4 aO1 = make_float4(0.f, 0.f, 0.f, 0.f);
        float4 aO2 = aO1, aT1 = aO1, aT2 = aO1;
        #pragma unroll 8
        for (int d = 0; d < D_; d++) {
            const float td = stTop[d];
            const int ix = d * 16 + og;
            uint2 v; __half2* vh = (__half2*)&v; float2 f0, f1;
            v = O2a[ix];
            f0 = __half22float2(vh[0]); f1 = __half22float2(vh[1]);
            aO1.x += td * f0.x; aO1.y += td * f0.y; aO1.z += td * f1.x; aO1.w += td * f1.y;
            v = O2b[ix];
            f0 = __half22float2(vh[0]); f1 = __half22float2(vh[1]);
            aO2.x += td * f0.x; aO2.y += td * f0.y; aO2.z += td * f1.x; aO2.w += td * f1.y;
            v = T2a[ix];
            f0 = __half22float2(vh[0]); f1 = __half22float2(vh[1]);
            aT1.x += td * f0.x; aT1.y += td * f0.y; aT1.z += td * f1.x; aT1.w += td * f1.y;
            v = T2b[ix];
            f0 = __half22float2(vh[0]); f1 = __half22float2(vh[1]);
            aT2.x += td * f0.x; aT2.y += td * f0.y; aT2.z += td * f1.x; aT2.w += td * f1.y;
        }

        // per-s softmax, weight by old state, stage partials
        float4 pO1 = softmax16(aO1);
        float4 pO2 = softmax16(aO2);
        float4 pT1 = softmax16(aT1);
        float4 pT2 = softmax16(aT2);
        const float st1 = state[s1], st2 = state[s2];
        float4 w;
        w.x = st1 * pO1.x + st2 * pO2.x; w.y = st1 * pO1.y + st2 * pO2.y;
        w.z = st1 * pO1.z + st2 * pO2.z; w.w = st1 * pO1.w + st2 * pO2.w;
        partO4[srow * 16 + og] = w;
        w.x = st1 * pT1.x + st2 * pT2.x; w.y = st1 * pT1.y + st2 * pT2.y;
        w.z = st1 * pT1.z + st2 * pT2.z; w.w = st1 * pT1.w + st2 * pT2.w;
        partT4[srow * 16 + og] = w;
        __syncthreads();

        // ---- phase 3: reduce over s-rows -> out_prob, new_state
        if (tid < 64) {
            const float* pO = (const float*)partO4;
            const float* pT = (const float*)partT4;
            float so = 0.f, sn = 0.f;
            #pragma unroll
            for (int r = 0; r < 32; r++) {
                so += pO[r * 64 + tid];
                sn += pT[r * 64 + tid];
            }
            out[((size_t)b * TLEN_ + t) * NO_ + tid] = so;
            nstate[tid] = sn;
        }

        // ---- pointer update (pop then push), content update
        float p = 0.f, pd = 0.f;
        if (tid < K_) {
            p  = pointer[tid];
            pd = (tid < K_ - 1) ? pointer[tid + 1] : 0.f;
        }
        __syncthreads();
        const float pops  = scal[1];
        const float pushs = scal[0];
        if (tid < K_) {
            if (pops > THR_) p = pops * pd + (1.f - pops) * p;
            pointer[tid] = p;
        }
        __syncthreads();
        float pu = 0.f;
        if (tid < K_) pu = (tid > 0) ? pointer[tid - 1] : 0.f;
        __syncthreads();
        if (tid < K_) {
            float q = pushs * pu + (1.f - pushs) * p;
            wbuf[tid] = q;
            if (pushs > THR_) pointer[tid] = q;
        }
        __syncthreads();

        if (pushs > THR_) {
            for (int e = tid; e < K_ * D_; e += NTHREADS) {
                int k = e >> 6, d = e & 63;
                float wk = wbuf[k];
                content[e] = content[e] * (1.f - wk) + pushv[d] * wk;
            }
        }
        if (tid < S_) state[tid] = nstate[tid];
        __syncthreads();
    }
}

extern "C" void kernel_launch(void* const* d_in, const int* in_sizes, int n_in,
                              void* d_out, int out_size)
{
    const int*   seq   = (const int*)  d_in[0]; // input_seq [B,TLEN] int32
    const float* Tt    = (const float*)d_in[1]; // T  [S,I,D,S]
    const float* Ot    = (const float*)d_in[2]; // O  [S,I,D,NO]
    const float* pgate = (const float*)d_in[3]; // push_gate [S,I,1]
    const float* pop   = (const float*)d_in[4]; // pop_gate  [S,I,1]
    const float* pval  = (const float*)d_in[5]; // push_value [S,I,D]
    const float* initl = (const float*)d_in[6]; // init_logits [S]
    float* out = (float*)d_out;                 // [B,TLEN,NO]

    // prologue: fp32 -> fp16 weight conversion (device globals, no allocation)
    cvt_kernel<<<(unsigned)((TOTAL4 + 255) / 256), 256>>>(Tt, Ot);

    fpt_kernel<<<B_, NTHREADS>>>(seq, pgate, pop, pval, initl, out);
}

// round 4
// speedup vs baseline: 1.6014x; 1.1776x over previous
#include <cuda_runtime.h>
#include <cuda_fp16.h>
#include <cstdint>
#include <math.h>

#define S_    64
#define I_    128
#define NO_   64
#define K_    64
#define D_    64
#define B_    64
#define TLEN_ 256
#define THR_  0.01f
#define NTHREADS 512

#define WELEM  ((size_t)S_ * I_ * D_ * S_)   // 33,554,432 per weight tensor
#define TOTAL4 (WELEM / 4)

// fp16 copies of T and O, built once per launch (device globals: no allocation)
__device__ __half g_Th[WELEM];
__device__ __half g_Oh[WELEM];

__global__ __launch_bounds__(256)
void cvt_kernel(const float* __restrict__ Ts, const float* __restrict__ Os) {
    size_t i = (size_t)blockIdx.x * blockDim.x + threadIdx.x;
    if (i >= TOTAL4) return;
    float4 a = ((const float4*)Ts)[i];
    float4 b = ((const float4*)Os)[i];
    __half2 a0 = __floats2half2_rn(a.x, a.y);
    __half2 a1 = __floats2half2_rn(a.z, a.w);
    __half2 b0 = __floats2half2_rn(b.x, b.y);
    __half2 b1 = __floats2half2_rn(b.z, b.w);
    uint2 ua, ub;
    ua.x = *(unsigned*)&a0; ua.y = *(unsigned*)&a1;
    ub.x = *(unsigned*)&b0; ub.y = *(unsigned*)&b1;
    ((uint2*)g_Th)[i] = ua;
    ((uint2*)g_Oh)[i] = ub;
}

// ---------- cluster helpers ----------
__device__ __forceinline__ unsigned int s2u(const void* p) {
    unsigned int a;
    asm("{ .reg .u64 t; cvta.to.shared.u64 t, %1; cvt.u32.u64 %0, t; }" : "=r"(a) : "l"(p));
    return a;
}
__device__ __forceinline__ unsigned int ctarank() {
    unsigned int r; asm("mov.u32 %0, %%cluster_ctarank;" : "=r"(r)); return r;
}
__device__ __forceinline__ void arrive_peer(unsigned int local_bar, unsigned int peer) {
    asm volatile(
        "{ .reg .b32 ra;\n\t"
        "mapa.shared::cluster.u32 ra, %0, %1;\n\t"
        "mbarrier.arrive.release.cluster.shared::cluster.b64 _, [ra]; }"
        :: "r"(local_bar), "r"(peer) : "memory");
}
__device__ __forceinline__ void wait_bar_cluster(unsigned int bar, unsigned int parity) {
    asm volatile(
        "{\n\t.reg .pred P;\n\t"
        "WL%=:\n\t"
        "mbarrier.try_wait.parity.acquire.cluster.shared::cta.b64 P, [%0], %1, 0x989680;\n\t"
        "@P bra.uni WD%=;\n\t"
        "bra.uni WL%=;\n\t"
        "WD%=:\n\t}"
        :: "r"(bar), "r"(parity) : "memory");
}
__device__ __forceinline__ float ld_peer_f32(unsigned int local_addr, unsigned int peer) {
    unsigned int ra, v;
    asm("mapa.shared::cluster.u32 %0, %1, %2;" : "=r"(ra) : "r"(local_addr), "r"(peer));
    asm volatile("ld.shared::cluster.b32 %0, [%1];" : "=r"(v) : "r"(ra) : "memory");
    return __uint_as_float(v);
}

// softmax over 64 values held as float4 by a 16-thread subgroup
__device__ __forceinline__ float4 softmax16(float4 a) {
    float m = fmaxf(fmaxf(a.x, a.y), fmaxf(a.z, a.w));
    #pragma unroll
    for (int o = 8; o > 0; o >>= 1)
        m = fmaxf(m, __shfl_xor_sync(0xffffffffu, m, o, 16));
    float4 e;
    e.x = expf(a.x - m); e.y = expf(a.y - m);
    e.z = expf(a.z - m); e.w = expf(a.w - m);
    float s = e.x + e.y + e.z + e.w;
    #pragma unroll
    for (int o = 8; o > 0; o >>= 1)
        s += __shfl_xor_sync(0xffffffffu, s, o, 16);
    float inv = 1.0f / s;
    e.x *= inv; e.y *= inv; e.z *= inv; e.w *= inv;
    return e;
}

__global__ __launch_bounds__(NTHREADS, 1) __cluster_dims__(2, 1, 1)
void fpt_kernel(const int*   __restrict__ seq,
                const float* __restrict__ pg,   // [S,I,1]
                const float* __restrict__ pp,   // [S,I,1]
                const float* __restrict__ pv,   // [S,I,D]
                const float* __restrict__ initl,// [S]
                float*       __restrict__ out)  // [B,TLEN,NO]
{
    __shared__ float  content[K_ * D_];
    __shared__ float4 partO4[32 * 16];
    __shared__ float4 partT4[32 * 16];
    __shared__ float  state[S_];
    __shared__ float  nstate[S_];
    __shared__ float  pointer[K_];
    __shared__ float  stTop[D_];
    __shared__ float  wbuf[K_];
    __shared__ float  pushv[D_];
    __shared__ float  scal[4];
    __shared__ float  exch[2][128];
    __shared__ __align__(8) unsigned long long bar[2];

    const int tid   = threadIdx.x;
    const unsigned int rank = ctarank();
    const unsigned int peer = rank ^ 1u;
    const int b     = blockIdx.x >> 1;
    const int sbase = (int)rank * 32;     // this CTA owns s in [sbase, sbase+32)
    const int og    = tid & 15;           // 16 x float4 = 64 outputs
    const int srow  = tid >> 4;           // 0..31 (local s-row)
    const int s     = sbase + srow;

    // ---- init carry (redundant per CTA, bitwise identical)
    if (tid < S_) stTop[tid] = initl[tid];
    __syncthreads();
    if (tid == 0) {
        float m = -1e30f;
        for (int i = 0; i < S_; i++) m = fmaxf(m, stTop[i]);
        float ssum = 0.f;
        for (int i = 0; i < S_; i++) { float e = expf(stTop[i] - m); wbuf[i] = e; ssum += e; }
        scal[2] = ssum;
        asm volatile("mbarrier.init.shared.b64 [%0], 1;" :: "r"(s2u(&bar[0])) : "memory");
        asm volatile("mbarrier.init.shared.b64 [%0], 1;" :: "r"(s2u(&bar[1])) : "memory");
    }
    __syncthreads();
    if (tid < S_) state[tid] = wbuf[tid] / scal[2];
    for (int e = tid; e < K_ * D_; e += NTHREADS) content[e] = 0.f;
    if (tid < K_) pointer[tid] = (tid == 0) ? 1.f : 0.f;
    __syncthreads();

    // cluster barrier: peer's mbarriers initialized before any arrive
    asm volatile("barrier.cluster.arrive.aligned;" ::: "memory");
    asm volatile("barrier.cluster.wait.aligned;" ::: "memory");

    const unsigned int bar_u[2] = { s2u(&bar[0]), s2u(&bar[1]) };
    const unsigned int exch_u   = s2u(&exch[0][0]);

    for (int t = 0; t < TLEN_; t++) {
        const int sym = seq[b * TLEN_ + t];
        const int p   = t & 1;
        const unsigned int par = (unsigned int)(t >> 1) & 1u;

        // ---- phase 1: stack_top, gate scalars, push_v (disjoint warps, redundant)
        if (tid < D_) {
            float acc = 0.f;
            #pragma unroll
            for (int k = 0; k < K_; k++) acc += pointer[k] * content[k * D_ + tid];
            stTop[tid] = acc;
        } else if (tid < 96) {               // warp 2: push_s
            int l = tid - 64;
            float a = pg[l * I_ + sym] * state[l] + pg[(l + 32) * I_ + sym] * state[l + 32];
            #pragma unroll
            for (int o = 16; o > 0; o >>= 1) a += __shfl_xor_sync(0xffffffffu, a, o);
            if (l == 0) scal[0] = 1.f / (1.f + expf(-a));
        } else if (tid < 128) {              // warp 3: pop_s
            int l = tid - 96;
            float a = pp[l * I_ + sym] * state[l] + pp[(l + 32) * I_ + sym] * state[l + 32];
            #pragma unroll
            for (int o = 16; o > 0; o >>= 1) a += __shfl_xor_sync(0xffffffffu, a, o);
            if (l == 0) scal[1] = 1.f / (1.f + expf(-a));
        } else if (tid < 192) {              // warps 4-5: push_v = tanh(state @ pv[:,sym,:])
            int d = tid - 128;
            float acc = 0.f;
            #pragma unroll 8
            for (int ss = 0; ss < S_; ss++) acc += state[ss] * pv[(ss * I_ + sym) * D_ + d];
            pushv[d] = tanhf(acc);
        }
        __syncthreads();

        // ---- phase 2: this CTA streams its 32 s-rows of O and T
        const uint2* O2 = (const uint2*)(g_Oh + (size_t)(s * I_ + sym) * 4096);
        const uint2* T2 = (const uint2*)(g_Th + (size_t)(s * I_ + sym) * 4096);
        float4 aO = make_float4(0.f, 0.f, 0.f, 0.f);
        float4 aT = aO;
        #pragma unroll 8
        for (int d = 0; d < D_; d++) {
            const float td = stTop[d];
            const int ix = d * 16 + og;
            uint2 v; __half2* vh = (__half2*)&v; float2 f0, f1;
            v = O2[ix];
            f0 = __half22float2(vh[0]); f1 = __half22float2(vh[1]);
            aO.x += td * f0.x; aO.y += td * f0.y; aO.z += td * f1.x; aO.w += td * f1.y;
            v = T2[ix];
            f0 = __half22float2(vh[0]); f1 = __half22float2(vh[1]);
            aT.x += td * f0.x; aT.y += td * f0.y; aT.z += td * f1.x; aT.w += td * f1.y;
        }

        float4 pO = softmax16(aO);
        float4 pT = softmax16(aT);
        const float st = state[s];
        float4 w;
        w.x = st * pO.x; w.y = st * pO.y; w.z = st * pO.z; w.w = st * pO.w;
        partO4[srow * 16 + og] = w;
        w.x = st * pT.x; w.y = st * pT.y; w.z = st * pT.z; w.w = st * pT.w;
        partT4[srow * 16 + og] = w;
        __syncthreads();

        // ---- phase 3: local s-reduction -> exchange partials across the cluster
        float mine = 0.f;
        if (tid < 64) {
            const float* pOf = (const float*)partO4;
            #pragma unroll
            for (int r = 0; r < 32; r++) mine += pOf[r * 64 + tid];
            exch[p][tid] = mine;
        } else if (tid < 128) {
            const int c = tid - 64;
            const float* pTf = (const float*)partT4;
            #pragma unroll
            for (int r = 0; r < 32; r++) mine += pTf[r * 64 + c];
            exch[p][tid] = mine;
        }
        __syncthreads();
        if (tid == 0) arrive_peer(bar_u[p], peer);
        if (tid < 128) {
            wait_bar_cluster(bar_u[p], par);
            float pval_ = ld_peer_f32(exch_u + (unsigned int)(p * 128 + tid) * 4u, peer);
            if (tid < 64) {
                if (rank == 0)
                    out[((size_t)b * TLEN_ + t) * NO_ + tid] = mine + pval_;
            } else {
                nstate[tid - 64] = mine + pval_;
            }
        }

        // ---- pointer update (pop then push), content update (redundant per CTA)
        float pcur = 0.f, pd = 0.f;
        if (tid < K_) {
            pcur = pointer[tid];
            pd   = (tid < K_ - 1) ? pointer[tid + 1] : 0.f;
        }
        __syncthreads();
        const float pops  = scal[1];
        const float pushs = scal[0];
        if (tid < K_) {
            if (pops > THR_) pcur = pops * pd + (1.f - pops) * pcur;
            pointer[tid] = pcur;
        }
        __syncthreads();
        float pu = 0.f;
        if (tid < K_) pu = (tid > 0) ? pointer[tid - 1] : 0.f;
        __syncthreads();
        if (tid < K_) {
            float q = pushs * pu + (1.f - pushs) * pcur;
            wbuf[tid] = q;
            if (pushs > THR_) pointer[tid] = q;
        }
        __syncthreads();

        if (pushs > THR_) {
            for (int e = tid; e < K_ * D_; e += NTHREADS) {
                int k = e >> 6, d = e & 63;
                float wk = wbuf[k];
                content[e] = content[e] * (1.f - wk) + pushv[d] * wk;
            }
        }
        if (tid < S_) state[tid] = nstate[tid];
        __syncthreads();
    }

    // cluster barrier before exit: peer may still read our smem this step
    asm volatile("barrier.cluster.arrive.aligned;" ::: "memory");
    asm volatile("barrier.cluster.wait.aligned;" ::: "memory");
}

extern "C" void kernel_launch(void* const* d_in, const int* in_sizes, int n_in,
                              void* d_out, int out_size)
{
    const int*   seq   = (const int*)  d_in[0]; // input_seq [B,TLEN] int32
    const float* Tt    = (const float*)d_in[1]; // T  [S,I,D,S]
    const float* Ot    = (const float*)d_in[2]; // O  [S,I,D,NO]
    const float* pgate = (const float*)d_in[3]; // push_gate [S,I,1]
    const float* pop   = (const float*)d_in[4]; // pop_gate  [S,I,1]
    const float* pval  = (const float*)d_in[5]; // push_value [S,I,D]
    const float* initl = (const float*)d_in[6]; // init_logits [S]
    float* out = (float*)d_out;                 // [B,TLEN,NO]

    cvt_kernel<<<(unsigned)((TOTAL4 + 255) / 256), 256>>>(Tt, Ot);
    fpt_kernel<<<2 * B_, NTHREADS>>>(seq, pgate, pop, pval, initl, out);
}

// round 5
// speedup vs baseline: 1.7824x; 1.1130x over previous
#include <cuda_runtime.h>
#include <cuda_fp16.h>
#include <cstdint>
#include <math.h>

#define S_    64
#define I_    128
#define NO_   64
#define K_    64
#define D_    64
#define B_    64
#define TLEN_ 256
#define THR_  0.01f
#define NTHREADS 1024

#define WELEM  ((size_t)S_ * I_ * D_ * S_)
#define TOTAL4 (WELEM / 4)

__device__ __half g_Th[WELEM];
__device__ __half g_Oh[WELEM];

__global__ __launch_bounds__(256)
void cvt_kernel(const float* __restrict__ Ts, const float* __restrict__ Os) {
    size_t i = (size_t)blockIdx.x * blockDim.x + threadIdx.x;
    if (i >= TOTAL4) return;
    float4 a = ((const float4*)Ts)[i];
    float4 b = ((const float4*)Os)[i];
    __half2 a0 = __floats2half2_rn(a.x, a.y);
    __half2 a1 = __floats2half2_rn(a.z, a.w);
    __half2 b0 = __floats2half2_rn(b.x, b.y);
    __half2 b1 = __floats2half2_rn(b.z, b.w);
    uint2 ua, ub;
    ua.x = *(unsigned*)&a0; ua.y = *(unsigned*)&a1;
    ub.x = *(unsigned*)&b0; ub.y = *(unsigned*)&b1;
    ((uint2*)g_Th)[i] = ua;
    ((uint2*)g_Oh)[i] = ub;
}

// ---------- helpers ----------
__device__ __forceinline__ unsigned int s2u(const void* p) {
    unsigned int a;
    asm("{ .reg .u64 t; cvta.to.shared.u64 t, %1; cvt.u32.u64 %0, t; }" : "=r"(a) : "l"(p));
    return a;
}
__device__ __forceinline__ unsigned int ctarank() {
    unsigned int r; asm("mov.u32 %0, %%cluster_ctarank;" : "=r"(r)); return r;
}
__device__ __forceinline__ void arrive_peer(unsigned int local_bar, unsigned int peer) {
    asm volatile(
        "{ .reg .b32 ra;\n\t"
        "mapa.shared::cluster.u32 ra, %0, %1;\n\t"
        "mbarrier.arrive.release.cluster.shared::cluster.b64 _, [ra]; }"
        :: "r"(local_bar), "r"(peer) : "memory");
}
__device__ __forceinline__ void wait_bar_cluster(unsigned int bar, unsigned int parity) {
    asm volatile(
        "{\n\t.reg .pred P;\n\t"
        "WL%=:\n\t"
        "mbarrier.try_wait.parity.acquire.cluster.shared::cta.b64 P, [%0], %1, 0x989680;\n\t"
        "@P bra.uni WD%=;\n\t"
        "bra.uni WL%=;\n\t"
        "WD%=:\n\t}"
        :: "r"(bar), "r"(parity) : "memory");
}
__device__ __forceinline__ float ld_peer_f32(unsigned int local_addr, unsigned int peer) {
    unsigned int ra, v;
    asm("mapa.shared::cluster.u32 %0, %1, %2;" : "=r"(ra) : "r"(local_addr), "r"(peer));
    asm volatile("ld.shared::cluster.b32 %0, [%1];" : "=r"(v) : "r"(ra) : "memory");
    return __uint_as_float(v);
}
__device__ __forceinline__ float tanh_fast(float x) {
    float y; asm("tanh.approx.f32 %0, %1;" : "=f"(y) : "f"(x)); return y;
}

// softmax over 64 values held as float4 by each 16-lane group (fast exp)
__device__ __forceinline__ float4 softmax16(float4 a) {
    float m = fmaxf(fmaxf(a.x, a.y), fmaxf(a.z, a.w));
    #pragma unroll
    for (int o = 8; o > 0; o >>= 1)
        m = fmaxf(m, __shfl_xor_sync(0xffffffffu, m, o, 16));
    float4 e;
    e.x = __expf(a.x - m); e.y = __expf(a.y - m);
    e.z = __expf(a.z - m); e.w = __expf(a.w - m);
    float s = e.x + e.y + e.z + e.w;
    #pragma unroll
    for (int o = 8; o > 0; o >>= 1)
        s += __shfl_xor_sync(0xffffffffu, s, o, 16);
    float inv = 1.0f / s;
    e.x *= inv; e.y *= inv; e.z *= inv; e.w *= inv;
    return e;
}

__global__ __launch_bounds__(NTHREADS, 1) __cluster_dims__(2, 1, 1)
void fpt_kernel(const int*   __restrict__ seq,
                const float* __restrict__ pg,   // [S,I,1]
                const float* __restrict__ pp,   // [S,I,1]
                const float* __restrict__ pv,   // [S,I,D]
                const float* __restrict__ initl,// [S]
                float*       __restrict__ out)  // [B,TLEN,NO]
{
    __shared__ float  content[K_ * D_];
    __shared__ float4 partO4[32 * 16];
    __shared__ float4 partT4[32 * 16];
    __shared__ float  state[S_];
    __shared__ float  nstate[S_];
    __shared__ float  pointer[K_];
    __shared__ float  stTop[D_];
    __shared__ float  wbuf[K_];
    __shared__ float  pushv[D_];
    __shared__ float  scal[4];
    __shared__ float  exch[2][128];
    __shared__ int    seq_s[TLEN_];
    __shared__ __align__(8) unsigned long long bar[2];

    const int tid   = threadIdx.x;
    const int wid   = tid >> 5;           // 0..31 == s-row this warp owns
    const int lane  = tid & 31;
    const int og    = lane & 15;          // float4 group over outputs
    const int dh    = lane >> 4;          // d-half (0/1)
    const unsigned int rank = ctarank();
    const unsigned int peer = rank ^ 1u;
    const int b     = blockIdx.x >> 1;
    const int s     = (int)rank * 32 + wid;

    // ---- init
    if (tid < S_) stTop[tid] = initl[tid];
    for (int e = tid; e < TLEN_; e += NTHREADS) seq_s[e] = seq[b * TLEN_ + e];
    __syncthreads();
    if (tid == 0) {
        float m = -1e30f;
        for (int i = 0; i < S_; i++) m = fmaxf(m, stTop[i]);
        float ssum = 0.f;
        for (int i = 0; i < S_; i++) { float e = expf(stTop[i] - m); wbuf[i] = e; ssum += e; }
        scal[2] = ssum;
        asm volatile("mbarrier.init.shared.b64 [%0], 1;" :: "r"(s2u(&bar[0])) : "memory");
        asm volatile("mbarrier.init.shared.b64 [%0], 1;" :: "r"(s2u(&bar[1])) : "memory");
    }
    __syncthreads();
    if (tid < S_) state[tid] = wbuf[tid] / scal[2];
    for (int e = tid; e < K_ * D_; e += NTHREADS) content[e] = 0.f;
    if (tid < K_) pointer[tid] = (tid == 0) ? 1.f : 0.f;
    __syncthreads();

    asm volatile("barrier.cluster.arrive.aligned;" ::: "memory");
    asm volatile("barrier.cluster.wait.aligned;" ::: "memory");

    const unsigned int bar_u[2] = { s2u(&bar[0]), s2u(&bar[1]) };
    const unsigned int exch_u   = s2u(&exch[0][0]);

    for (int t = 0; t < TLEN_; t++) {
        const int sym = seq_s[t];
        const int p   = t & 1;
        const unsigned int par = (unsigned int)(t >> 1) & 1u;

        // ---- phase 1 (disjoint warps, split contractions, shuffle-combined)
        if (wid < 4) {
            // stack_top: d = wid*16 + og, k-half = dh, 32 k's each
            const int d = wid * 16 + og;
            const int kb = dh * 32;
            float acc = 0.f;
            #pragma unroll 8
            for (int j = 0; j < 32; j++)
                acc += pointer[kb + j] * content[(kb + j) * D_ + d];
            acc += __shfl_xor_sync(0xffffffffu, acc, 16);
            if (dh == 0) stTop[d] = acc;
        } else if (wid == 4) {               // push_s
            float a = pg[lane * I_ + sym] * state[lane] + pg[(lane + 32) * I_ + sym] * state[lane + 32];
            #pragma unroll
            for (int o = 16; o > 0; o >>= 1) a += __shfl_xor_sync(0xffffffffu, a, o);
            if (lane == 0) scal[0] = 1.f / (1.f + __expf(-a));
        } else if (wid == 5) {               // pop_s
            float a = pp[lane * I_ + sym] * state[lane] + pp[(lane + 32) * I_ + sym] * state[lane + 32];
            #pragma unroll
            for (int o = 16; o > 0; o >>= 1) a += __shfl_xor_sync(0xffffffffu, a, o);
            if (lane == 0) scal[1] = 1.f / (1.f + __expf(-a));
        } else if (wid < 10) {               // push_v: d = (wid-6)*16 + og, state-half = dh
            const int d = (wid - 6) * 16 + og;
            const int sb = dh * 32;
            float acc = 0.f;
            #pragma unroll 8
            for (int j = 0; j < 32; j++)
                acc += state[sb + j] * pv[((sb + j) * I_ + sym) * D_ + d];
            acc += __shfl_xor_sync(0xffffffffu, acc, 16);
            if (dh == 0) pushv[d] = tanh_fast(acc);
        }
        __syncthreads();

        // ---- phase 2: warp = one s-row; lanes split d into two halves of 32
        const uint2* O2 = (const uint2*)(g_Oh + (size_t)(s * I_ + sym) * 4096) + dh * 512 + og;
        const uint2* T2 = (const uint2*)(g_Th + (size_t)(s * I_ + sym) * 4096) + dh * 512 + og;
        const float* tT = stTop + dh * 32;
        float4 aO = make_float4(0.f, 0.f, 0.f, 0.f);
        float4 aT = aO;
        #pragma unroll 8
        for (int d = 0; d < 32; d++) {
            const float td = tT[d];
            uint2 v; __half2* vh = (__half2*)&v; float2 f0, f1;
            v = O2[d * 16];
            f0 = __half22float2(vh[0]); f1 = __half22float2(vh[1]);
            aO.x += td * f0.x; aO.y += td * f0.y; aO.z += td * f1.x; aO.w += td * f1.y;
            v = T2[d * 16];
            f0 = __half22float2(vh[0]); f1 = __half22float2(vh[1]);
            aT.x += td * f0.x; aT.y += td * f0.y; aT.z += td * f1.x; aT.w += td * f1.y;
        }
        // combine d-halves
        aO.x += __shfl_xor_sync(0xffffffffu, aO.x, 16);
        aO.y += __shfl_xor_sync(0xffffffffu, aO.y, 16);
        aO.z += __shfl_xor_sync(0xffffffffu, aO.z, 16);
        aO.w += __shfl_xor_sync(0xffffffffu, aO.w, 16);
        aT.x += __shfl_xor_sync(0xffffffffu, aT.x, 16);
        aT.y += __shfl_xor_sync(0xffffffffu, aT.y, 16);
        aT.z += __shfl_xor_sync(0xffffffffu, aT.z, 16);
        aT.w += __shfl_xor_sync(0xffffffffu, aT.w, 16);

        float4 pO = softmax16(aO);
        float4 pT = softmax16(aT);
        const float st = state[s];
        if (dh == 0) {
            float4 w;
            w.x = st * pO.x; w.y = st * pO.y; w.z = st * pO.z; w.w = st * pO.w;
            partO4[wid * 16 + og] = w;
            w.x = st * pT.x; w.y = st * pT.y; w.z = st * pT.z; w.w = st * pT.w;
            partT4[wid * 16 + og] = w;
        }
        __syncthreads();

        // ---- phase 3: local s-reduction -> cluster exchange
        float mine = 0.f;
        if (tid < 64) {
            const float* pOf = (const float*)partO4;
            #pragma unroll
            for (int r = 0; r < 32; r++) mine += pOf[r * 64 + tid];
            exch[p][tid] = mine;
        } else if (tid < 128) {
            const int c = tid - 64;
            const float* pTf = (const float*)partT4;
            #pragma unroll
            for (int r = 0; r < 32; r++) mine += pTf[r * 64 + c];
            exch[p][tid] = mine;
        }
        __syncthreads();
        if (tid == 0) arrive_peer(bar_u[p], peer);
        if (tid < 128) {
            wait_bar_cluster(bar_u[p], par);
            float pval_ = ld_peer_f32(exch_u + (unsigned int)(p * 128 + tid) * 4u, peer);
            if (tid < 64) {
                if (rank == 0)
                    out[((size_t)b * TLEN_ + t) * NO_ + tid] = mine + pval_;
            } else {
                nstate[tid - 64] = mine + pval_;
            }
        }

        // ---- pointer update (pop then push), content update (redundant per CTA)
        float pcur = 0.f, pd = 0.f;
        if (tid < K_) {
            pcur = pointer[tid];
            pd   = (tid < K_ - 1) ? pointer[tid + 1] : 0.f;
        }
        __syncthreads();
        const float pops  = scal[1];
        const float pushs = scal[0];
        if (tid < K_) {
            if (pops > THR_) pcur = pops * pd + (1.f - pops) * pcur;
            pointer[tid] = pcur;
        }
        __syncthreads();
        float pu = 0.f;
        if (tid < K_) pu = (tid > 0) ? pointer[tid - 1] : 0.f;
        __syncthreads();
        if (tid < K_) {
            float q = pushs * pu + (1.f - pushs) * pcur;
            wbuf[tid] = q;
            if (pushs > THR_) pointer[tid] = q;
        }
        __syncthreads();

        if (pushs > THR_) {
            #pragma unroll
            for (int e = tid; e < K_ * D_; e += NTHREADS) {
                int k = e >> 6, d = e & 63;
                float wk = wbuf[k];
                content[e] = content[e] * (1.f - wk) + pushv[d] * wk;
            }
        }
        if (tid < S_) state[tid] = nstate[tid];
        __syncthreads();
    }

    asm volatile("barrier.cluster.arrive.aligned;" ::: "memory");
    asm volatile("barrier.cluster.wait.aligned;" ::: "memory");
}

extern "C" void kernel_launch(void* const* d_in, const int* in_sizes, int n_in,
                              void* d_out, int out_size)
{
    const int*   seq   = (const int*)  d_in[0];
    const float* Tt    = (const float*)d_in[1];
    const float* Ot    = (const float*)d_in[2];
    const float* pgate = (const float*)d_in[3];
    const float* pop   = (const float*)d_in[4];
    const float* pval  = (const float*)d_in[5];
    const float* initl = (const float*)d_in[6];
    float* out = (float*)d_out;

    cvt_kernel<<<(unsigned)((TOTAL4 + 255) / 256), 256>>>(Tt, Ot);
    fpt_kernel<<<2 * B_, NTHREADS>>>(seq, pgate, pop, pval, initl, out);
}

// round 6
// speedup vs baseline: 2.2858x; 1.2824x over previous
#include <cuda_runtime.h>
#include <cuda_fp16.h>
#include <cstdint>
#include <math.h>

#define S_    64
#define I_    128
#define NO_   64
#define K_    64
#define D_    64
#define B_    64
#define TLEN_ 256
#define THR_  0.01f
#define NTHREADS 1024

#define WELEM  ((size_t)S_ * I_ * D_ * S_)
#define TOTAL4 (WELEM / 4)

__device__ __half g_Th[WELEM];
__device__ __half g_Oh[WELEM];

__global__ __launch_bounds__(256)
void cvt_kernel(const float* __restrict__ Ts, const float* __restrict__ Os) {
    size_t i = (size_t)blockIdx.x * blockDim.x + threadIdx.x;
    if (i >= TOTAL4) return;
    float4 a = ((const float4*)Ts)[i];
    float4 b = ((const float4*)Os)[i];
    __half2 a0 = __floats2half2_rn(a.x, a.y);
    __half2 a1 = __floats2half2_rn(a.z, a.w);
    __half2 b0 = __floats2half2_rn(b.x, b.y);
    __half2 b1 = __floats2half2_rn(b.z, b.w);
    uint2 ua, ub;
    ua.x = *(unsigned*)&a0; ua.y = *(unsigned*)&a1;
    ub.x = *(unsigned*)&b0; ub.y = *(unsigned*)&b1;
    ((uint2*)g_Th)[i] = ua;
    ((uint2*)g_Oh)[i] = ub;
}

// ---------- helpers ----------
__device__ __forceinline__ unsigned int s2u(const void* p) {
    unsigned int a;
    asm("{ .reg .u64 t; cvta.to.shared.u64 t, %1; cvt.u32.u64 %0, t; }" : "=r"(a) : "l"(p));
    return a;
}
__device__ __forceinline__ unsigned int ctarank() {
    unsigned int r; asm("mov.u32 %0, %%cluster_ctarank;" : "=r"(r)); return r;
}
__device__ __forceinline__ void arrive_peer(unsigned int local_bar, unsigned int peer) {
    asm volatile(
        "{ .reg .b32 ra;\n\t"
        "mapa.shared::cluster.u32 ra, %0, %1;\n\t"
        "mbarrier.arrive.release.cluster.shared::cluster.b64 _, [ra]; }"
        :: "r"(local_bar), "r"(peer) : "memory");
}
__device__ __forceinline__ void wait_bar_cluster(unsigned int bar, unsigned int parity) {
    asm volatile(
        "{\n\t.reg .pred P;\n\t"
        "WL%=:\n\t"
        "mbarrier.try_wait.parity.acquire.cluster.shared::cta.b64 P, [%0], %1, 0x989680;\n\t"
        "@P bra.uni WD%=;\n\t"
        "bra.uni WL%=;\n\t"
        "WD%=:\n\t}"
        :: "r"(bar), "r"(parity) : "memory");
}
__device__ __forceinline__ float ld_peer_f32(unsigned int local_addr, unsigned int peer) {
    unsigned int ra, v;
    asm("mapa.shared::cluster.u32 %0, %1, %2;" : "=r"(ra) : "r"(local_addr), "r"(peer));
    asm volatile("ld.shared::cluster.b32 %0, [%1];" : "=r"(v) : "r"(ra) : "memory");
    return __uint_as_float(v);
}
__device__ __forceinline__ float tanh_fast(float x) {
    float y; asm("tanh.approx.f32 %0, %1;" : "=f"(y) : "f"(x)); return y;
}

// in-place softmax over 64 values: 8 per lane across an 8-lane group
__device__ __forceinline__ void softmax8(float* a) {
    float m = a[0];
    #pragma unroll
    for (int j = 1; j < 8; j++) m = fmaxf(m, a[j]);
    #pragma unroll
    for (int o = 4; o > 0; o >>= 1) m = fmaxf(m, __shfl_xor_sync(0xffffffffu, m, o, 8));
    float s = 0.f;
    #pragma unroll
    for (int j = 0; j < 8; j++) { a[j] = __expf(a[j] - m); s += a[j]; }
    #pragma unroll
    for (int o = 4; o > 0; o >>= 1) s += __shfl_xor_sync(0xffffffffu, s, o, 8);
    float inv = 1.0f / s;
    #pragma unroll
    for (int j = 0; j < 8; j++) a[j] *= inv;
}

__global__ __launch_bounds__(NTHREADS, 1) __cluster_dims__(2, 1, 1)
void fpt_kernel(const int*   __restrict__ seq,
                const float* __restrict__ pg,
                const float* __restrict__ pp,
                const float* __restrict__ pv,
                const float* __restrict__ initl,
                float*       __restrict__ out)
{
    __shared__ float   content[K_ * D_];
    __shared__ float   partO[32 * 64];
    __shared__ float   partT[32 * 64];
    __shared__ float   state[S_];
    __shared__ float   nstate[S_];
    __shared__ float   pointer[K_];
    __shared__ __half2 stTop2[D_];
    __shared__ float   wbuf[K_];
    __shared__ float   pushv[D_];
    __shared__ float   scal[4];
    __shared__ float   exch[2][128];
    __shared__ int     seq_s[TLEN_ + 1];
    __shared__ __align__(8) unsigned long long bar[2];

    const int tid   = threadIdx.x;
    const int wid   = tid >> 5;
    const int lane  = tid & 31;
    const int lc    = lane & 7;     // col block (8 halves)
    const int lr    = lane >> 3;    // row-in-group-of-4
    const unsigned int rank = ctarank();
    const unsigned int peer = rank ^ 1u;
    const int b     = blockIdx.x >> 1;
    const int s     = (int)rank * 32 + wid;

    // ---- init
    if (tid < S_) wbuf[tid] = initl[tid];
    for (int e = tid; e <= TLEN_; e += NTHREADS)
        seq_s[e] = (e < TLEN_) ? seq[b * TLEN_ + e] : 0;
    __syncthreads();
    if (tid == 0) {
        float m = -1e30f;
        for (int i = 0; i < S_; i++) m = fmaxf(m, wbuf[i]);
        float ssum = 0.f;
        for (int i = 0; i < S_; i++) { float e = expf(wbuf[i] - m); pushv[i] = e; ssum += e; }
        scal[2] = ssum;
        asm volatile("mbarrier.init.shared.b64 [%0], 1;" :: "r"(s2u(&bar[0])) : "memory");
        asm volatile("mbarrier.init.shared.b64 [%0], 1;" :: "r"(s2u(&bar[1])) : "memory");
    }
    __syncthreads();
    if (tid < S_) state[tid] = pushv[tid] / scal[2];
    for (int e = tid; e < K_ * D_; e += NTHREADS) content[e] = 0.f;
    if (tid < K_) pointer[tid] = (tid == 0) ? 1.f : 0.f;
    __syncthreads();

    asm volatile("barrier.cluster.arrive.aligned;" ::: "memory");
    asm volatile("barrier.cluster.wait.aligned;" ::: "memory");

    const unsigned int bar_u[2] = { s2u(&bar[0]), s2u(&bar[1]) };
    const unsigned int exch_u   = s2u(&exch[0][0]);

    // ================= tail block (computes stTop2, gates, pushv for symbol ns) =====
    #define TAIL_BLOCK(ns)                                                          \
    {                                                                               \
        const int nsym = (ns);                                                      \
        if (wid < 2) {                                                              \
            const int d = wid * 32 + lane;                                          \
            float a0 = 0.f, a1 = 0.f;                                               \
            _Pragma("unroll 8")                                                     \
            for (int k = 0; k < 32; k++) {                                          \
                a0 += pointer[k]      * content[k * D_ + d];                        \
                a1 += pointer[k + 32] * content[(k + 32) * D_ + d];                 \
            }                                                                       \
            stTop2[d] = __float2half2_rn(a0 + a1);                                  \
        } else if (wid == 2) {                                                      \
            float a = pg[lane * I_ + nsym] * state[lane]                            \
                    + pg[(lane + 32) * I_ + nsym] * state[lane + 32];               \
            _Pragma("unroll")                                                       \
            for (int o = 16; o > 0; o >>= 1) a += __shfl_xor_sync(0xffffffffu, a, o); \
            if (lane == 0) scal[0] = 1.f / (1.f + __expf(-a));                      \
        } else if (wid == 3) {                                                      \
            float a = pp[lane * I_ + nsym] * state[lane]                            \
                    + pp[(lane + 32) * I_ + nsym] * state[lane + 32];               \
            _Pragma("unroll")                                                       \
            for (int o = 16; o > 0; o >>= 1) a += __shfl_xor_sync(0xffffffffu, a, o); \
            if (lane == 0) scal[1] = 1.f / (1.f + __expf(-a));                      \
        } else if (wid < 8) {                                                       \
            const int d  = (wid - 4) * 16 + (lane & 15);                            \
            const int sb = (lane >> 4) * 32;                                        \
            float acc = 0.f;                                                        \
            _Pragma("unroll 8")                                                     \
            for (int j = 0; j < 32; j++)                                            \
                acc += state[sb + j] * pv[((sb + j) * I_ + nsym) * D_ + d];         \
            acc += __shfl_xor_sync(0xffffffffu, acc, 16);                           \
            if ((lane >> 4) == 0) pushv[d] = tanh_fast(acc);                        \
        }                                                                           \
    }

    // prologue: tail for t = 0
    TAIL_BLOCK(seq_s[0]);

    for (int t = 0; t < TLEN_; t++) {
        const int sym = seq_s[t];
        const int p   = t & 1;
        const unsigned int par = (unsigned int)(t >> 1) & 1u;

        __syncthreads();   // B4/loop-top: stTop2, scal, pushv valid

        // ---- phase 2: warp = one s-row; LDG.128 + HFMA2, fp32 flush every 8 d
        {
            const uint4* O4 = (const uint4*)(g_Oh + (size_t)(s * I_ + sym) * 4096);
            const uint4* T4 = (const uint4*)(g_Th + (size_t)(s * I_ + sym) * 4096);
            float fO[8] = {0,0,0,0,0,0,0,0};
            float fT[8] = {0,0,0,0,0,0,0,0};
            const __half2 hz = __float2half2_rn(0.f);
            #pragma unroll
            for (int chunk = 0; chunk < 2; chunk++) {
                __half2 hO[4] = {hz, hz, hz, hz};
                __half2 hT[4] = {hz, hz, hz, hz};
                #pragma unroll
                for (int i = 0; i < 8; i++) {
                    const int ii = chunk * 8 + i;
                    const __half2 td2 = stTop2[ii * 4 + lr];
                    uint4 v = O4[ii * 32 + lane];
                    hO[0] = __hfma2(td2, *(__half2*)&v.x, hO[0]);
                    hO[1] = __hfma2(td2, *(__half2*)&v.y, hO[1]);
                    hO[2] = __hfma2(td2, *(__half2*)&v.z, hO[2]);
                    hO[3] = __hfma2(td2, *(__half2*)&v.w, hO[3]);
                    uint4 u = T4[ii * 32 + lane];
                    hT[0] = __hfma2(td2, *(__half2*)&u.x, hT[0]);
                    hT[1] = __hfma2(td2, *(__half2*)&u.y, hT[1]);
                    hT[2] = __hfma2(td2, *(__half2*)&u.z, hT[2]);
                    hT[3] = __hfma2(td2, *(__half2*)&u.w, hT[3]);
                }
                #pragma unroll
                for (int c = 0; c < 4; c++) {
                    float2 f = __half22float2(hO[c]);
                    fO[2 * c] += f.x; fO[2 * c + 1] += f.y;
                    f = __half22float2(hT[c]);
                    fT[2 * c] += f.x; fT[2 * c + 1] += f.y;
                }
            }
            // combine the 4 row-groups (lanes differing in bits 3,4)
            #pragma unroll
            for (int j = 0; j < 8; j++) {
                fO[j] += __shfl_xor_sync(0xffffffffu, fO[j], 8);
                fO[j] += __shfl_xor_sync(0xffffffffu, fO[j], 16);
                fT[j] += __shfl_xor_sync(0xffffffffu, fT[j], 8);
                fT[j] += __shfl_xor_sync(0xffffffffu, fT[j], 16);
            }
            softmax8(fO);
            softmax8(fT);
            const float st = state[s];
            if (lr == 0) {
                float4 w;
                w.x = st * fO[0]; w.y = st * fO[1]; w.z = st * fO[2]; w.w = st * fO[3];
                *(float4*)&partO[wid * 64 + lc * 8]     = w;
                w.x = st * fO[4]; w.y = st * fO[5]; w.z = st * fO[6]; w.w = st * fO[7];
                *(float4*)&partO[wid * 64 + lc * 8 + 4] = w;
                w.x = st * fT[0]; w.y = st * fT[1]; w.z = st * fT[2]; w.w = st * fT[3];
                *(float4*)&partT[wid * 64 + lc * 8]     = w;
                w.x = st * fT[4]; w.y = st * fT[5]; w.z = st * fT[6]; w.w = st * fT[7];
                *(float4*)&partT[wid * 64 + lc * 8 + 4] = w;
            }
        }
        __syncthreads();   // B1: partials ready

        // ---- phase 3 (warps 0-3): reduce + cluster exchange;  warp 10: pointer update
        if (tid < 128) {
            float mine = 0.f;
            if (tid < 64) {
                #pragma unroll
                for (int r = 0; r < 32; r++) mine += partO[r * 64 + tid];
            } else {
                const int c = tid - 64;
                #pragma unroll
                for (int r = 0; r < 32; r++) mine += partT[r * 64 + c];
            }
            exch[p][tid] = mine;
            asm volatile("bar.sync 1, 128;" ::: "memory");
            if (tid == 0) arrive_peer(bar_u[p], peer);
            wait_bar_cluster(bar_u[p], par);
            float pval_ = ld_peer_f32(exch_u + (unsigned int)(p * 128 + tid) * 4u, peer);
            if (tid < 64) {
                if (rank == 0)
                    out[((size_t)b * TLEN_ + t) * NO_ + tid] = mine + pval_;
            } else {
                nstate[tid - 64] = mine + pval_;
            }
        } else if (wid == 10) {
            // pointer update, 2 elements per lane, shuffle-based
            const int i0 = lane * 2;
            float p0 = pointer[i0], p1 = pointer[i0 + 1];
            const float pops  = scal[1];
            const float pushs = scal[0];
            // pop
            float d1 = __shfl_down_sync(0xffffffffu, p0, 1);
            if (lane == 31) d1 = 0.f;
            if (pops > THR_) {
                p0 = pops * p1 + (1.f - pops) * p0;
                p1 = pops * d1 + (1.f - pops) * p1;
            }
            // push (uses post-pop pointer)
            float u0 = __shfl_up_sync(0xffffffffu, p1, 1);
            if (lane == 0) u0 = 0.f;
            float q0 = pushs * u0 + (1.f - pushs) * p0;
            float q1 = pushs * p0 + (1.f - pushs) * p1;
            wbuf[i0] = q0; wbuf[i0 + 1] = q1;
            if (pushs > THR_) { p0 = q0; p1 = q1; }
            pointer[i0] = p0; pointer[i0 + 1] = p1;
        }
        __syncthreads();   // B2: nstate, out, pointer, wbuf ready

        // ---- content update + state commit
        {
            const float pushs = scal[0];
            if (pushs > THR_) {
                #pragma unroll
                for (int e = tid; e < K_ * D_; e += NTHREADS) {
                    int k = e >> 6, d = e & 63;
                    float wk = wbuf[k];
                    content[e] = content[e] * (1.f - wk) + pushv[d] * wk;
                }
            }
            if (tid < S_) state[tid] = nstate[tid];
        }
        __syncthreads();   // B3: content/state committed

        // ---- tail: compute stTop2, gates, pushv for step t+1
        TAIL_BLOCK(seq_s[t + 1]);
    }

    asm volatile("barrier.cluster.arrive.aligned;" ::: "memory");
    asm volatile("barrier.cluster.wait.aligned;" ::: "memory");
}

extern "C" void kernel_launch(void* const* d_in, const int* in_sizes, int n_in,
                              void* d_out, int out_size)
{
    const int*   seq   = (const int*)  d_in[0];
    const float* Tt    = (const float*)d_in[1];
    const float* Ot    = (const float*)d_in[2];
    const float* pgate = (const float*)d_in[3];
    const float* pop   = (const float*)d_in[4];
    const float* pval  = (const float*)d_in[5];
    const float* initl = (const float*)d_in[6];
    float* out = (float*)d_out;

    cvt_kernel<<<(unsigned)((TOTAL4 + 255) / 256), 256>>>(Tt, Ot);
    fpt_kernel<<<2 * B_, NTHREADS>>>(seq, pgate, pop, pval, initl, out);
}